// round 7
// baseline (speedup 1.0000x reference)
#include <cuda_runtime.h>
#include <cuda_fp16.h>
#include <math.h>

#define NN 100000
#define NF 64
#define NC 40
#define NE 1600000
#define NODES_BLK 64
#define GEMM_THREADS 160          // 16 node-quads x 10 col-quads
#define GEMM_BLOCKS ((NN + NODES_BLK - 1) / NODES_BLK)     // 1563
#define HIST_BLOCKS ((NE + GEMM_THREADS - 1) / GEMM_THREADS) // 10000
#define NBLK_SCAN 98              // ceil(100000/1024)

// device-global scratch
__device__ __align__(16) __half2 g_yh[NN * 32];  // y fp16, rows padded to 128B (slots 0..19 used)
__device__ __align__(16) float   g_z[NN * NC];   // z = x@Wr + b
__device__ int g_cnt[NN];
__device__ int g_off[NN];
__device__ int g_cursor[NN];
__device__ int g_csr[NE];
__device__ unsigned long long g_tile[NBLK_SCAN]; // decoupled-lookback state
__device__ int g_is64;

#define FLAG_PARTIAL (1ull << 62)
#define FLAG_PREFIX  (2ull << 62)
#define VAL_MASK     ((1ull << 62) - 1)

// ---------------------------------------------------------------------------
// K0: detect index dtype + zero cnt + zero lookback tiles.
// ---------------------------------------------------------------------------
__global__ void __launch_bounds__(256) k_prep(const int* __restrict__ idx32) {
    int n = blockIdx.x * 256 + threadIdx.x;
    if (blockIdx.x == 0) {
        if (threadIdx.x == 0) {
            int odd_nonzero = 0;
            for (int i = 1; i < 128; i += 2)
                if (idx32[i] != 0) odd_nonzero++;
            g_is64 = (odd_nonzero == 0) ? 1 : 0;
        }
        if (threadIdx.x < NBLK_SCAN) g_tile[threadIdx.x] = 0ull;
    }
    if (n < NN) g_cnt[n] = 0;
}

// ---------------------------------------------------------------------------
__device__ __forceinline__ int load_idx(const void* raw, long long pos) {
    int v;
    if (g_is64) v = (int)((const long long*)raw)[pos];
    else        v = ((const int*)raw)[pos];
    return min(max(v, 0), NN - 1);
}

__device__ __forceinline__ unsigned long long pack2(float lo, float hi) {
    unsigned long long r;
    asm("mov.b64 %0, {%1, %2};" : "=l"(r) : "r"(__float_as_uint(lo)), "r"(__float_as_uint(hi)));
    return r;
}
__device__ __forceinline__ unsigned long long dup2(float v) {
    unsigned long long r;
    unsigned u = __float_as_uint(v);
    asm("mov.b64 %0, {%1, %1};" : "=l"(r) : "r"(u));
    return r;
}
__device__ __forceinline__ void fma2(unsigned long long& d, unsigned long long a,
                                     unsigned long long b) {
    asm("fma.rn.f32x2 %0, %1, %2, %0;" : "+l"(d) : "l"(a), "l"(b));
}
__device__ __forceinline__ float2 unpack2(unsigned long long p) {
    unsigned lo, hi;
    asm("mov.b64 {%0, %1}, %2;" : "=r"(lo), "=r"(hi) : "l"(p));
    return make_float2(__uint_as_float(lo), __uint_as_float(hi));
}

// ---------------------------------------------------------------------------
// K1: fused register-tiled dual GEMM (FFMA2) + degree histogram.
// gemm blocks: [0, GEMM_BLOCKS); hist blocks: the rest.
// ---------------------------------------------------------------------------
__global__ void __launch_bounds__(GEMM_THREADS) k_gemm_hist(const float* __restrict__ x,
                                                            const float* __restrict__ wl,
                                                            const float* __restrict__ bl,
                                                            const float* __restrict__ wr,
                                                            const void* __restrict__ idx_raw) {
    if (blockIdx.x >= GEMM_BLOCKS) {
        int e = (blockIdx.x - GEMM_BLOCKS) * GEMM_THREADS + threadIdx.x;
        if (e < NE) atomicAdd(&g_cnt[load_idx(idx_raw, (long long)NE + e)], 1);
        return;
    }

    __shared__ float s_xT[NF][NODES_BLK];   // [k][node]
    __shared__ float s_wl[NF * NC];
    __shared__ float s_wr[NF * NC];
    __shared__ float s_b[NC];

    const int tid = threadIdx.x;
    const int n0 = blockIdx.x * NODES_BLK;

    for (int i = tid; i < NF * NC; i += GEMM_THREADS) {
        s_wl[i] = wl[i];
        s_wr[i] = wr[i];
    }
    if (tid < NC) s_b[tid] = bl[tid];

    for (int i = tid; i < NODES_BLK * 16; i += GEMM_THREADS) {
        int node = i & (NODES_BLK - 1);
        int kq = i >> 6;
        int gn = n0 + node;
        float4 v = make_float4(0.f, 0.f, 0.f, 0.f);
        if (gn < NN) v = reinterpret_cast<const float4*>(x)[gn * 16 + kq];
        s_xT[kq * 4 + 0][node] = v.x;
        s_xT[kq * 4 + 1][node] = v.y;
        s_xT[kq * 4 + 2][node] = v.z;
        s_xT[kq * 4 + 3][node] = v.w;
    }
    __syncthreads();

    const int nq = tid / 10;        // 0..15
    const int cq = tid - nq * 10;   // 0..9

    unsigned long long ay[4][2] = {}, az[4][2] = {};
#pragma unroll 4
    for (int k = 0; k < NF; k++) {
        const float4 xv  = *reinterpret_cast<const float4*>(&s_xT[k][nq * 4]);
        const float4 wl4 = *reinterpret_cast<const float4*>(&s_wl[k * NC + cq * 4]);
        const float4 wr4 = *reinterpret_cast<const float4*>(&s_wr[k * NC + cq * 4]);
        unsigned long long wlp0 = pack2(wl4.x, wl4.y), wlp1 = pack2(wl4.z, wl4.w);
        unsigned long long wrp0 = pack2(wr4.x, wr4.y), wrp1 = pack2(wr4.z, wr4.w);
        const float xs[4] = {xv.x, xv.y, xv.z, xv.w};
#pragma unroll
        for (int i = 0; i < 4; i++) {
            unsigned long long xp = dup2(xs[i]);
            fma2(ay[i][0], xp, wlp0);
            fma2(ay[i][1], xp, wlp1);
            fma2(az[i][0], xp, wrp0);
            fma2(az[i][1], xp, wrp1);
        }
    }

#pragma unroll
    for (int i = 0; i < 4; i++) {
        int n = n0 + nq * 4 + i;
        if (n >= NN) continue;
        float2 y0 = unpack2(ay[i][0]), y1 = unpack2(ay[i][1]);
        float2 z0 = unpack2(az[i][0]), z1 = unpack2(az[i][1]);
        float4 zb;
        zb.x = z0.x + s_b[cq * 4 + 0];
        zb.y = z0.y + s_b[cq * 4 + 1];
        zb.z = z1.x + s_b[cq * 4 + 2];
        zb.w = z1.y + s_b[cq * 4 + 3];
        reinterpret_cast<float4*>(&g_z[n * NC])[cq] = zb;
        g_yh[n * 32 + cq * 2 + 0] = __floats2half2_rn(y0.x, y0.y);
        g_yh[n * 32 + cq * 2 + 1] = __floats2half2_rn(y1.x, y1.y);
    }
}

// ---------------------------------------------------------------------------
// K2: single-pass exclusive scan (decoupled lookback), 98 tiles of 1024.
// Writes g_off and g_cursor.
// ---------------------------------------------------------------------------
__global__ void __launch_bounds__(256) k_scan() {
    __shared__ int s_ws[8];
    __shared__ int s_woff[8];
    __shared__ int s_prefix;
    int tid = threadIdx.x, lane = tid & 31, w = tid >> 5;
    int b = blockIdx.x;
    int base = b * 1024 + tid * 4;

    int v0 = (base + 0 < NN) ? g_cnt[base + 0] : 0;
    int v1 = (base + 1 < NN) ? g_cnt[base + 1] : 0;
    int v2 = (base + 2 < NN) ? g_cnt[base + 2] : 0;
    int v3 = (base + 3 < NN) ? g_cnt[base + 3] : 0;
    int tsum = v0 + v1 + v2 + v3;
    int incl = tsum;
#pragma unroll
    for (int off = 1; off < 32; off <<= 1) {
        int t = __shfl_up_sync(0xFFFFFFFFu, incl, off);
        if (lane >= off) incl += t;
    }
    if (lane == 31) s_ws[w] = incl;
    __syncthreads();

    if (tid == 0) {
        int run = 0;
#pragma unroll
        for (int i = 0; i < 8; i++) { s_woff[i] = run; run += s_ws[i]; }
        int total = run;
        if (b == 0) {
            atomicExch(&g_tile[0], FLAG_PREFIX | (unsigned long long)total);
            s_prefix = 0;
        } else {
            atomicExch(&g_tile[b], FLAG_PARTIAL | (unsigned long long)total);
            long long prefix = 0;
            int p = b - 1;
            while (p >= 0) {
                unsigned long long v = atomicAdd(&g_tile[p], 0ull);
                unsigned long long f = v & ~VAL_MASK;
                if (f == FLAG_PREFIX) { prefix += (long long)(v & VAL_MASK); break; }
                if (f == FLAG_PARTIAL) { prefix += (long long)(v & VAL_MASK); p--; }
                // else spin on same p
            }
            atomicExch(&g_tile[b], FLAG_PREFIX | (unsigned long long)(prefix + total));
            s_prefix = (int)prefix;
        }
    }
    __syncthreads();

    int excl = s_prefix + s_woff[w] + (incl - tsum);
    if (base + 0 < NN) { g_off[base + 0] = excl;                g_cursor[base + 0] = excl; }
    if (base + 1 < NN) { g_off[base + 1] = excl + v0;           g_cursor[base + 1] = excl + v0; }
    if (base + 2 < NN) { g_off[base + 2] = excl + v0 + v1;      g_cursor[base + 2] = excl + v0 + v1; }
    if (base + 3 < NN) { g_off[base + 3] = excl + v0 + v1 + v2; g_cursor[base + 3] = excl + v0 + v1 + v2; }
}

// ---------------------------------------------------------------------------
// K3: CSR fill
// ---------------------------------------------------------------------------
__global__ void __launch_bounds__(256) k_fill(const void* __restrict__ idx_raw) {
    int e = blockIdx.x * 256 + threadIdx.x;
    if (e >= NE) return;
    int src = load_idx(idx_raw, e);
    int dst = load_idx(idx_raw, (long long)NE + e);
    g_csr[atomicAdd(&g_cursor[dst], 1)] = src;
}

// ---------------------------------------------------------------------------
// K4: fused gather-mean + z + log_softmax. Warp per node; lanes 0..19 carry
// column pairs (2l, 2l+1) -> 80B (3 sectors) per edge.
// ---------------------------------------------------------------------------
__global__ void __launch_bounds__(256) k_fused(float* __restrict__ out) {
    int gtid = blockIdx.x * 256 + threadIdx.x;
    int node = gtid >> 5;
    int lane = threadIdx.x & 31;
    if (node >= NN) return;

    int base = g_off[node];
    int deg  = g_cnt[node];
    bool valid = lane < 20;

    float2 acc = make_float2(0.f, 0.f);
    for (int j0 = 0; j0 < deg; j0 += 32) {
        int e = (j0 + lane < deg) ? g_csr[base + j0 + lane] : 0;
        int m = min(32, deg - j0);
        for (int k = 0; k < m; k++) {
            int src = __shfl_sync(0xFFFFFFFFu, e, k);
            if (valid) {
                float2 f = __half22float2(g_yh[src * 32 + lane]);
                acc.x += f.x;
                acc.y += f.y;
            }
        }
    }

    float inv = 1.0f / fmaxf((float)deg, 1.0f);
    const float NEG = -3.0e38f;
    float2 z2 = valid ? reinterpret_cast<const float2*>(&g_z[node * NC])[lane]
                      : make_float2(0.f, 0.f);
    float va = valid ? fmaf(acc.x, inv, z2.x) : NEG;
    float vb = valid ? fmaf(acc.y, inv, z2.y) : NEG;

    float mx = fmaxf(va, vb);
#pragma unroll
    for (int off = 16; off > 0; off >>= 1)
        mx = fmaxf(mx, __shfl_xor_sync(0xFFFFFFFFu, mx, off));

    float s = valid ? (__expf(va - mx) + __expf(vb - mx)) : 0.0f;
#pragma unroll
    for (int off = 16; off > 0; off >>= 1)
        s += __shfl_xor_sync(0xFFFFFFFFu, s, off);

    float lse = mx + logf(s);
    if (valid) {
        float2 o = make_float2(va - lse, vb - lse);
        reinterpret_cast<float2*>(&out[node * NC])[lane] = o;
    }
}

extern "C" void kernel_launch(void* const* d_in, const int* in_sizes, int n_in,
                              void* d_out, int out_size) {
    const float* x   = (const float*)d_in[0];
    const void*  idx = d_in[1];
    const float* wl  = (const float*)d_in[2];
    const float* bl  = (const float*)d_in[3];
    const float* wr  = (const float*)d_in[4];
    float* out = (float*)d_out;

    k_prep<<<(NN + 255) / 256, 256>>>((const int*)idx);
    k_gemm_hist<<<GEMM_BLOCKS + HIST_BLOCKS, GEMM_THREADS>>>(x, wl, bl, wr, idx);
    k_scan<<<NBLK_SCAN, 256>>>();
    k_fill<<<(NE + 255) / 256, 256>>>(idx);
    k_fused<<<(NN * 32 + 255) / 256, 256>>>(out);
}

// round 8
// speedup vs baseline: 1.0090x; 1.0090x over previous
#include <cuda_runtime.h>
#include <cuda_fp16.h>
#include <math.h>

#define NN 100000
#define NF 64
#define NC 40
#define NE 1600000
#define NODES_BLK 64
#define GEMM_THREADS 160          // 16 node-quads x 10 col-quads
#define NBLK_SCAN 98              // ceil(100000/1024)

// device-global scratch
__device__ __align__(16) __half2 g_yh[NN * 32];  // y fp16, rows padded to 128B (slots 0..19 used)
__device__ __align__(16) float   g_z[NN * NC];   // z = x@Wr + b
__device__ int g_cnt[NN];
__device__ int g_off[NN];
__device__ int g_cursor[NN];
__device__ int g_csr[NE];
__device__ unsigned long long g_tile[NBLK_SCAN]; // decoupled-lookback state
__device__ int g_is64;

#define FLAG_PARTIAL (1ull << 62)
#define FLAG_PREFIX  (2ull << 62)
#define VAL_MASK     ((1ull << 62) - 1)

// ---------------------------------------------------------------------------
// B-chain K0: zero cnt + lookback tiles, detect index dtype.
// ---------------------------------------------------------------------------
__global__ void __launch_bounds__(256) k_zero(const int* __restrict__ idx32) {
    int n = blockIdx.x * 256 + threadIdx.x;
    if (blockIdx.x == 0) {
        if (threadIdx.x == 0) {
            int odd_nonzero = 0;
            for (int i = 1; i < 128; i += 2)
                if (idx32[i] != 0) odd_nonzero++;
            g_is64 = (odd_nonzero == 0) ? 1 : 0;
        }
        if (threadIdx.x < NBLK_SCAN) g_tile[threadIdx.x] = 0ull;
    }
    if (n < NN) g_cnt[n] = 0;
}

// ---------------------------------------------------------------------------
__device__ __forceinline__ int load_idx(const void* raw, long long pos) {
    int v;
    if (g_is64) v = (int)((const long long*)raw)[pos];
    else        v = ((const int*)raw)[pos];
    return min(max(v, 0), NN - 1);
}

// ---------------------------------------------------------------------------
// A-chain: register-tiled dual GEMM (plain FMA, proven R6 version).
// ---------------------------------------------------------------------------
__global__ void __launch_bounds__(GEMM_THREADS) k_gemm(const float* __restrict__ x,
                                                       const float* __restrict__ wl,
                                                       const float* __restrict__ bl,
                                                       const float* __restrict__ wr) {
    __shared__ float s_xT[NF][NODES_BLK];   // [k][node]
    __shared__ float s_wl[NF * NC];
    __shared__ float s_wr[NF * NC];
    __shared__ float s_b[NC];

    const int tid = threadIdx.x;
    const int n0 = blockIdx.x * NODES_BLK;

    for (int i = tid; i < NF * NC; i += GEMM_THREADS) {
        s_wl[i] = wl[i];
        s_wr[i] = wr[i];
    }
    if (tid < NC) s_b[tid] = bl[tid];

    for (int i = tid; i < NODES_BLK * 16; i += GEMM_THREADS) {
        int node = i & (NODES_BLK - 1);
        int kq = i >> 6;
        int gn = n0 + node;
        float4 v = make_float4(0.f, 0.f, 0.f, 0.f);
        if (gn < NN) v = reinterpret_cast<const float4*>(x)[gn * 16 + kq];
        s_xT[kq * 4 + 0][node] = v.x;
        s_xT[kq * 4 + 1][node] = v.y;
        s_xT[kq * 4 + 2][node] = v.z;
        s_xT[kq * 4 + 3][node] = v.w;
    }
    __syncthreads();

    const int nq = tid / 10;        // 0..15
    const int cq = tid - nq * 10;   // 0..9

    float ay[4][4] = {}, az[4][4] = {};
#pragma unroll 4
    for (int k = 0; k < NF; k++) {
        const float4 xv  = *reinterpret_cast<const float4*>(&s_xT[k][nq * 4]);
        const float4 wl4 = *reinterpret_cast<const float4*>(&s_wl[k * NC + cq * 4]);
        const float4 wr4 = *reinterpret_cast<const float4*>(&s_wr[k * NC + cq * 4]);
        const float xs[4] = {xv.x, xv.y, xv.z, xv.w};
        const float ws[4] = {wl4.x, wl4.y, wl4.z, wl4.w};
        const float vs[4] = {wr4.x, wr4.y, wr4.z, wr4.w};
#pragma unroll
        for (int i = 0; i < 4; i++)
#pragma unroll
            for (int j = 0; j < 4; j++) {
                ay[i][j] = fmaf(xs[i], ws[j], ay[i][j]);
                az[i][j] = fmaf(xs[i], vs[j], az[i][j]);
            }
    }

#pragma unroll
    for (int i = 0; i < 4; i++) {
        int n = n0 + nq * 4 + i;
        if (n >= NN) continue;
        float4 zb;
        zb.x = az[i][0] + s_b[cq * 4 + 0];
        zb.y = az[i][1] + s_b[cq * 4 + 1];
        zb.z = az[i][2] + s_b[cq * 4 + 2];
        zb.w = az[i][3] + s_b[cq * 4 + 3];
        reinterpret_cast<float4*>(&g_z[n * NC])[cq] = zb;
        g_yh[n * 32 + cq * 2 + 0] = __floats2half2_rn(ay[i][0], ay[i][1]);
        g_yh[n * 32 + cq * 2 + 1] = __floats2half2_rn(ay[i][2], ay[i][3]);
    }
}

// ---------------------------------------------------------------------------
// B-chain: degree histogram.
// ---------------------------------------------------------------------------
__global__ void __launch_bounds__(256) k_hist(const void* __restrict__ idx_raw) {
    int e = blockIdx.x * 256 + threadIdx.x;
    if (e >= NE) return;
    atomicAdd(&g_cnt[load_idx(idx_raw, (long long)NE + e)], 1);
}

// ---------------------------------------------------------------------------
// B-chain: single-pass exclusive scan (decoupled lookback). Writes off+cursor.
// ---------------------------------------------------------------------------
__global__ void __launch_bounds__(256) k_scan() {
    __shared__ int s_ws[8];
    __shared__ int s_woff[8];
    __shared__ int s_prefix;
    int tid = threadIdx.x, lane = tid & 31, w = tid >> 5;
    int b = blockIdx.x;
    int base = b * 1024 + tid * 4;

    int v0 = (base + 0 < NN) ? g_cnt[base + 0] : 0;
    int v1 = (base + 1 < NN) ? g_cnt[base + 1] : 0;
    int v2 = (base + 2 < NN) ? g_cnt[base + 2] : 0;
    int v3 = (base + 3 < NN) ? g_cnt[base + 3] : 0;
    int tsum = v0 + v1 + v2 + v3;
    int incl = tsum;
#pragma unroll
    for (int off = 1; off < 32; off <<= 1) {
        int t = __shfl_up_sync(0xFFFFFFFFu, incl, off);
        if (lane >= off) incl += t;
    }
    if (lane == 31) s_ws[w] = incl;
    __syncthreads();

    if (tid == 0) {
        int run = 0;
#pragma unroll
        for (int i = 0; i < 8; i++) { s_woff[i] = run; run += s_ws[i]; }
        int total = run;
        if (b == 0) {
            atomicExch(&g_tile[0], FLAG_PREFIX | (unsigned long long)total);
            s_prefix = 0;
        } else {
            atomicExch(&g_tile[b], FLAG_PARTIAL | (unsigned long long)total);
            long long prefix = 0;
            int p = b - 1;
            while (p >= 0) {
                unsigned long long v = atomicAdd(&g_tile[p], 0ull);
                unsigned long long f = v & ~VAL_MASK;
                if (f == FLAG_PREFIX) { prefix += (long long)(v & VAL_MASK); break; }
                if (f == FLAG_PARTIAL) { prefix += (long long)(v & VAL_MASK); p--; }
            }
            atomicExch(&g_tile[b], FLAG_PREFIX | (unsigned long long)(prefix + total));
            s_prefix = (int)prefix;
        }
    }
    __syncthreads();

    int excl = s_prefix + s_woff[w] + (incl - tsum);
    if (base + 0 < NN) { g_off[base + 0] = excl;                g_cursor[base + 0] = excl; }
    if (base + 1 < NN) { g_off[base + 1] = excl + v0;           g_cursor[base + 1] = excl + v0; }
    if (base + 2 < NN) { g_off[base + 2] = excl + v0 + v1;      g_cursor[base + 2] = excl + v0 + v1; }
    if (base + 3 < NN) { g_off[base + 3] = excl + v0 + v1 + v2; g_cursor[base + 3] = excl + v0 + v1 + v2; }
}

// ---------------------------------------------------------------------------
// B-chain: CSR fill.
// ---------------------------------------------------------------------------
__global__ void __launch_bounds__(256) k_fill(const void* __restrict__ idx_raw) {
    int e = blockIdx.x * 256 + threadIdx.x;
    if (e >= NE) return;
    int src = load_idx(idx_raw, e);
    int dst = load_idx(idx_raw, (long long)NE + e);
    g_csr[atomicAdd(&g_cursor[dst], 1)] = src;
}

// ---------------------------------------------------------------------------
// Join: fused gather-mean + z + log_softmax. Warp per node, lanes 0..19.
// ---------------------------------------------------------------------------
__global__ void __launch_bounds__(256) k_fused(float* __restrict__ out) {
    int gtid = blockIdx.x * 256 + threadIdx.x;
    int node = gtid >> 5;
    int lane = threadIdx.x & 31;
    if (node >= NN) return;

    int base = g_off[node];
    int deg  = g_cnt[node];
    bool valid = lane < 20;

    float2 acc = make_float2(0.f, 0.f);
    for (int j0 = 0; j0 < deg; j0 += 32) {
        int e = (j0 + lane < deg) ? g_csr[base + j0 + lane] : 0;
        int m = min(32, deg - j0);
        for (int k = 0; k < m; k++) {
            int src = __shfl_sync(0xFFFFFFFFu, e, k);
            if (valid) {
                float2 f = __half22float2(g_yh[src * 32 + lane]);
                acc.x += f.x;
                acc.y += f.y;
            }
        }
    }

    float inv = 1.0f / fmaxf((float)deg, 1.0f);
    const float NEG = -3.0e38f;
    float2 z2 = valid ? reinterpret_cast<const float2*>(&g_z[node * NC])[lane]
                      : make_float2(0.f, 0.f);
    float va = valid ? fmaf(acc.x, inv, z2.x) : NEG;
    float vb = valid ? fmaf(acc.y, inv, z2.y) : NEG;

    float mx = fmaxf(va, vb);
#pragma unroll
    for (int off = 16; off > 0; off >>= 1)
        mx = fmaxf(mx, __shfl_xor_sync(0xFFFFFFFFu, mx, off));

    float s = valid ? (__expf(va - mx) + __expf(vb - mx)) : 0.0f;
#pragma unroll
    for (int off = 16; off > 0; off >>= 1)
        s += __shfl_xor_sync(0xFFFFFFFFu, s, off);

    float lse = mx + logf(s);
    if (valid) {
        float2 o = make_float2(va - lse, vb - lse);
        reinterpret_cast<float2*>(&out[node * NC])[lane] = o;
    }
}

extern "C" void kernel_launch(void* const* d_in, const int* in_sizes, int n_in,
                              void* d_out, int out_size) {
    const float* x   = (const float*)d_in[0];
    const void*  idx = d_in[1];
    const float* wl  = (const float*)d_in[2];
    const float* bl  = (const float*)d_in[3];
    const float* wr  = (const float*)d_in[4];
    float* out = (float*)d_out;

    // one-time host resources (no device memory involved)
    static cudaStream_t s_aux = nullptr;
    static cudaEvent_t ev_fork = nullptr, ev_join = nullptr;
    if (s_aux == nullptr) {
        cudaStreamCreateWithFlags(&s_aux, cudaStreamNonBlocking);
        cudaEventCreateWithFlags(&ev_fork, cudaEventDisableTiming);
        cudaEventCreateWithFlags(&ev_join, cudaEventDisableTiming);
    }

    // fork: aux stream joins the capture
    cudaEventRecord(ev_fork, 0);
    cudaStreamWaitEvent(s_aux, ev_fork, 0);

    // chain A (default stream): dual GEMM
    k_gemm<<<(NN + NODES_BLK - 1) / NODES_BLK, GEMM_THREADS>>>(x, wl, bl, wr);

    // chain B (aux stream): CSR build
    k_zero<<<(NN + 255) / 256, 256, 0, s_aux>>>((const int*)idx);
    k_hist<<<(NE + 255) / 256, 256, 0, s_aux>>>(idx);
    k_scan<<<NBLK_SCAN, 256, 0, s_aux>>>();
    k_fill<<<(NE + 255) / 256, 256, 0, s_aux>>>(idx);

    // join
    cudaEventRecord(ev_join, s_aux);
    cudaStreamWaitEvent(0, ev_join, 0);

    k_fused<<<(NN * 32 + 255) / 256, 256>>>(out);
}

// round 9
// speedup vs baseline: 1.2369x; 1.2259x over previous
#include <cuda_runtime.h>
#include <cuda_fp16.h>
#include <math.h>

#define NN 100000
#define NF 64
#define NC 40
#define NE 1600000
#define NODES_BLK 64
#define NBLK_SCAN 98              // ceil(100000/1024)

// device-global scratch
__device__ __align__(16) __half2 g_yh[NN * 32];  // y fp16, rows padded to 128B
__device__ __align__(16) float   g_z[NN * NC];   // z = x@Wr + b
__device__ int g_cnt[NN];
__device__ int g_off[NN];
__device__ int g_cursor[NN];
__device__ int g_csr[NE];
__device__ int g_bsums[128];
__device__ int g_is64;

// ---------------------------------------------------------------------------
// K0: detect index dtype + zero g_cnt.
// ---------------------------------------------------------------------------
__global__ void __launch_bounds__(256) k_prep(const int* __restrict__ idx32) {
    if (blockIdx.x == 0 && threadIdx.x == 0) {
        int odd_nonzero = 0;
        for (int i = 1; i < 128; i += 2)
            if (idx32[i] != 0) odd_nonzero++;
        g_is64 = (odd_nonzero == 0) ? 1 : 0;
    }
    int n = blockIdx.x * 256 + threadIdx.x;
    if (n < NN) g_cnt[n] = 0;
}

// ---------------------------------------------------------------------------
__device__ __forceinline__ int load_idx(const void* raw, long long pos) {
    int v;
    if (g_is64) v = (int)((const long long*)raw)[pos];
    else        v = ((const int*)raw)[pos];
    return min(max(v, 0), NN - 1);
}

__device__ __forceinline__ unsigned cvt_tf32(float f) {
    unsigned r;
    asm("cvt.rna.tf32.f32 %0, %1;" : "=r"(r) : "f"(f));
    return r;
}

__device__ __forceinline__ void mma_tf32(float c[4], unsigned a0, unsigned a1,
                                         unsigned a2, unsigned a3,
                                         unsigned b0, unsigned b1) {
    asm("mma.sync.aligned.m16n8k8.row.col.f32.tf32.tf32.f32 "
        "{%0,%1,%2,%3}, {%4,%5,%6,%7}, {%8,%9}, {%0,%1,%2,%3};"
        : "+f"(c[0]), "+f"(c[1]), "+f"(c[2]), "+f"(c[3])
        : "r"(a0), "r"(a1), "r"(a2), "r"(a3), "r"(b0), "r"(b1));
}

// ---------------------------------------------------------------------------
// K1: dual GEMM on tensor cores (tf32 mma.sync, fp32 accumulate).
// Block = 128 threads (4 warps) x 64 nodes. Warp w: nodes [w*16, w*16+16),
// all 40 cols as 5 n-tiles of 8. K = 64 as 8 steps of 8.
// ---------------------------------------------------------------------------
__global__ void __launch_bounds__(128) k_gemm(const float* __restrict__ x,
                                              const float* __restrict__ wl,
                                              const float* __restrict__ bl,
                                              const float* __restrict__ wr) {
    __shared__ unsigned s_x[NODES_BLK][68];   // [node][k] tf32, pad 68 -> conflict-free A loads
    __shared__ unsigned s_wl[NF * NC];        // [k][c] tf32
    __shared__ unsigned s_wr[NF * NC];
    __shared__ float    s_b[NC];

    const int tid = threadIdx.x;
    const int n0 = blockIdx.x * NODES_BLK;

    for (int i = tid; i < NF * NC; i += 128) {
        s_wl[i] = cvt_tf32(wl[i]);
        s_wr[i] = cvt_tf32(wr[i]);
    }
    if (tid < NC) s_b[tid] = bl[tid];

    // stage x tile as tf32: 64 nodes x 16 float4
    for (int i = tid; i < NODES_BLK * 16; i += 128) {
        int node = i >> 4, kq = i & 15;
        int gn = n0 + node;
        float4 v = make_float4(0.f, 0.f, 0.f, 0.f);
        if (gn < NN) v = reinterpret_cast<const float4*>(x)[gn * 16 + kq];
        s_x[node][kq * 4 + 0] = cvt_tf32(v.x);
        s_x[node][kq * 4 + 1] = cvt_tf32(v.y);
        s_x[node][kq * 4 + 2] = cvt_tf32(v.z);
        s_x[node][kq * 4 + 3] = cvt_tf32(v.w);
    }
    __syncthreads();

    const int w = tid >> 5;          // warp 0..3
    const int lane = tid & 31;
    const int g = lane >> 2;         // groupID 0..7
    const int t = lane & 3;          // threadID_in_group 0..3
    const int wn = w * 16;           // warp node base (local)

    float cy[5][4] = {}, cz[5][4] = {};
#pragma unroll
    for (int k0 = 0; k0 < NF; k0 += 8) {
        unsigned a0 = s_x[wn + g][k0 + t];
        unsigned a1 = s_x[wn + g + 8][k0 + t];
        unsigned a2 = s_x[wn + g][k0 + t + 4];
        unsigned a3 = s_x[wn + g + 8][k0 + t + 4];
#pragma unroll
        for (int nt = 0; nt < 5; nt++) {
            unsigned b0 = s_wl[(k0 + t) * NC + nt * 8 + g];
            unsigned b1 = s_wl[(k0 + t + 4) * NC + nt * 8 + g];
            mma_tf32(cy[nt], a0, a1, a2, a3, b0, b1);
            unsigned d0 = s_wr[(k0 + t) * NC + nt * 8 + g];
            unsigned d1 = s_wr[(k0 + t + 4) * NC + nt * 8 + g];
            mma_tf32(cz[nt], a0, a1, a2, a3, d0, d1);
        }
    }

    // epilogue: c0,c1 -> (row g, cols 2t,2t+1); c2,c3 -> (row g+8, same cols)
#pragma unroll
    for (int nt = 0; nt < 5; nt++) {
        int c0 = nt * 8 + 2 * t;
        int nA = n0 + wn + g;
        int nB = nA + 8;
        if (nA < NN) {
            g_yh[nA * 32 + nt * 4 + t] = __floats2half2_rn(cy[nt][0], cy[nt][1]);
            float2 z = make_float2(cz[nt][0] + s_b[c0], cz[nt][1] + s_b[c0 + 1]);
            *reinterpret_cast<float2*>(&g_z[nA * NC + c0]) = z;
        }
        if (nB < NN) {
            g_yh[nB * 32 + nt * 4 + t] = __floats2half2_rn(cy[nt][2], cy[nt][3]);
            float2 z = make_float2(cz[nt][2] + s_b[c0], cz[nt][3] + s_b[c0 + 1]);
            *reinterpret_cast<float2*>(&g_z[nB * NC + c0]) = z;
        }
    }
    // zero y padding slots 20..31 (fused reads all 32 lanes)
    for (int i = tid; i < NODES_BLK * 12; i += 128) {
        int node = n0 + i / 12;
        int slot = 20 + i % 12;
        if (node < NN) g_yh[node * 32 + slot] = __floats2half2_rn(0.f, 0.f);
    }
}

// ---------------------------------------------------------------------------
__global__ void __launch_bounds__(256) k_hist(const void* __restrict__ idx_raw) {
    int e = blockIdx.x * 256 + threadIdx.x;
    if (e >= NE) return;
    atomicAdd(&g_cnt[load_idx(idx_raw, (long long)NE + e)], 1);
}

// K3a: 1024-elem exclusive scan per block
__global__ void __launch_bounds__(256) k_scan1() {
    __shared__ int s[256];
    int base = blockIdx.x * 1024 + threadIdx.x * 4;
    int v0 = (base + 0 < NN) ? g_cnt[base + 0] : 0;
    int v1 = (base + 1 < NN) ? g_cnt[base + 1] : 0;
    int v2 = (base + 2 < NN) ? g_cnt[base + 2] : 0;
    int v3 = (base + 3 < NN) ? g_cnt[base + 3] : 0;
    int tsum = v0 + v1 + v2 + v3;
    s[threadIdx.x] = tsum;
    __syncthreads();
#pragma unroll
    for (int off = 1; off < 256; off <<= 1) {
        int t = (threadIdx.x >= off) ? s[threadIdx.x - off] : 0;
        __syncthreads();
        s[threadIdx.x] += t;
        __syncthreads();
    }
    int excl = s[threadIdx.x] - tsum;
    if (base + 0 < NN) g_off[base + 0] = excl;
    if (base + 1 < NN) g_off[base + 1] = excl + v0;
    if (base + 2 < NN) g_off[base + 2] = excl + v0 + v1;
    if (base + 3 < NN) g_off[base + 3] = excl + v0 + v1 + v2;
    if (threadIdx.x == 255) g_bsums[blockIdx.x] = s[255];
}

// K3b: scan 98 block sums
__global__ void k_scan2() {
    __shared__ int s[128];
    int tid = threadIdx.x;
    int v = (tid < NBLK_SCAN) ? g_bsums[tid] : 0;
    s[tid] = v;
    __syncthreads();
#pragma unroll
    for (int off = 1; off < 128; off <<= 1) {
        int t = (tid >= off) ? s[tid - off] : 0;
        __syncthreads();
        s[tid] += t;
        __syncthreads();
    }
    if (tid < NBLK_SCAN) g_bsums[tid] = s[tid] - v;
}

// K3c: finalize offsets + init cursors
__global__ void __launch_bounds__(256) k_scan3() {
    int n = blockIdx.x * 256 + threadIdx.x;
    if (n >= NN) return;
    int o = g_off[n] + g_bsums[n >> 10];
    g_off[n] = o;
    g_cursor[n] = o;
}

// K4: CSR fill
__global__ void __launch_bounds__(256) k_fill(const void* __restrict__ idx_raw) {
    int e = blockIdx.x * 256 + threadIdx.x;
    if (e >= NE) return;
    int src = load_idx(idx_raw, e);
    int dst = load_idx(idx_raw, (long long)NE + e);
    g_csr[atomicAdd(&g_cursor[dst], 1)] = src;
}

// ---------------------------------------------------------------------------
// K5: fused gather-mean + z + log_softmax. Warp per node (R6-proven version).
// ---------------------------------------------------------------------------
__global__ void __launch_bounds__(256) k_fused(float* __restrict__ out) {
    int gtid = blockIdx.x * 256 + threadIdx.x;
    int node = gtid >> 5;
    int lane = threadIdx.x & 31;
    if (node >= NN) return;

    int base = g_off[node];
    int deg  = g_cnt[node];

    float2 acc = make_float2(0.f, 0.f);
    for (int j0 = 0; j0 < deg; j0 += 32) {
        int e = (j0 + lane < deg) ? g_csr[base + j0 + lane] : 0;
        int m = min(32, deg - j0);
        for (int k = 0; k < m; k++) {
            int src = __shfl_sync(0xFFFFFFFFu, e, k);
            float2 f = __half22float2(g_yh[src * 32 + lane]);
            acc.x += f.x;
            acc.y += f.y;
        }
    }

    float inv = 1.0f / fmaxf((float)deg, 1.0f);
    const float NEG = -3.0e38f;
    bool valid = lane < 20;
    float2 z2 = valid ? reinterpret_cast<const float2*>(&g_z[node * NC])[lane]
                      : make_float2(0.f, 0.f);
    float va = valid ? fmaf(acc.x, inv, z2.x) : NEG;
    float vb = valid ? fmaf(acc.y, inv, z2.y) : NEG;

    float mx = fmaxf(va, vb);
#pragma unroll
    for (int off = 16; off > 0; off >>= 1)
        mx = fmaxf(mx, __shfl_xor_sync(0xFFFFFFFFu, mx, off));

    float s = valid ? (__expf(va - mx) + __expf(vb - mx)) : 0.0f;
#pragma unroll
    for (int off = 16; off > 0; off >>= 1)
        s += __shfl_xor_sync(0xFFFFFFFFu, s, off);

    float lse = mx + logf(s);
    if (valid) {
        float2 o = make_float2(va - lse, vb - lse);
        reinterpret_cast<float2*>(&out[node * NC])[lane] = o;
    }
}

extern "C" void kernel_launch(void* const* d_in, const int* in_sizes, int n_in,
                              void* d_out, int out_size) {
    const float* x   = (const float*)d_in[0];
    const void*  idx = d_in[1];
    const float* wl  = (const float*)d_in[2];
    const float* bl  = (const float*)d_in[3];
    const float* wr  = (const float*)d_in[4];
    float* out = (float*)d_out;

    k_prep<<<(NN + 255) / 256, 256>>>((const int*)idx);
    k_gemm<<<(NN + NODES_BLK - 1) / NODES_BLK, 128>>>(x, wl, bl, wr);
    k_hist<<<(NE + 255) / 256, 256>>>(idx);
    k_scan1<<<NBLK_SCAN, 256>>>();
    k_scan2<<<1, 128>>>();
    k_scan3<<<(NN + 255) / 256, 256>>>();
    k_fill<<<(NE + 255) / 256, 256>>>(idx);
    k_fused<<<(NN * 32 + 255) / 256, 256>>>(out);
}

// round 10
// speedup vs baseline: 1.2618x; 1.0202x over previous
#include <cuda_runtime.h>
#include <cuda_fp16.h>
#include <math.h>

#define NN 100000
#define NF 64
#define NC 40
#define NE 1600000
#define NODES_BLK 64
#define NBLK_SCAN 98              // ceil(100000/1024)

// device-global scratch
__device__ __align__(16) __half2 g_yh[NN * 32];  // y fp16, rows padded to 128B
__device__ __align__(16) float   g_z[NN * NC];   // z = x@Wr + b
__device__ int g_cnt[NN];
__device__ int g_off[NN];
__device__ int g_cursor[NN];
__device__ int g_csr[NE];
__device__ int g_bsums[128];
__device__ int g_is64;

// ---------------------------------------------------------------------------
// K0: detect index dtype + zero g_cnt.
// ---------------------------------------------------------------------------
__global__ void __launch_bounds__(256) k_prep(const int* __restrict__ idx32) {
    if (blockIdx.x == 0 && threadIdx.x == 0) {
        int odd_nonzero = 0;
        for (int i = 1; i < 128; i += 2)
            if (idx32[i] != 0) odd_nonzero++;
        g_is64 = (odd_nonzero == 0) ? 1 : 0;
    }
    int n = blockIdx.x * 256 + threadIdx.x;
    if (n < NN) g_cnt[n] = 0;
}

// ---------------------------------------------------------------------------
__device__ __forceinline__ int clampn(int v) { return min(max(v, 0), NN - 1); }

// load 4 consecutive indices starting at element pos (pos % 4 == 0)
__device__ __forceinline__ void load_idx4(const void* raw, long long pos, int o[4]) {
    if (g_is64) {
        const longlong2* p = (const longlong2*)raw;
        longlong2 a = p[pos / 2];
        longlong2 b = p[pos / 2 + 1];
        o[0] = clampn((int)a.x); o[1] = clampn((int)a.y);
        o[2] = clampn((int)b.x); o[3] = clampn((int)b.y);
    } else {
        int4 v = ((const int4*)raw)[pos / 4];
        o[0] = clampn(v.x); o[1] = clampn(v.y);
        o[2] = clampn(v.z); o[3] = clampn(v.w);
    }
}

__device__ __forceinline__ unsigned cvt_tf32(float f) {
    unsigned r;
    asm("cvt.rna.tf32.f32 %0, %1;" : "=r"(r) : "f"(f));
    return r;
}

__device__ __forceinline__ void mma_tf32(float c[4], unsigned a0, unsigned a1,
                                         unsigned a2, unsigned a3,
                                         unsigned b0, unsigned b1) {
    asm("mma.sync.aligned.m16n8k8.row.col.f32.tf32.tf32.f32 "
        "{%0,%1,%2,%3}, {%4,%5,%6,%7}, {%8,%9}, {%0,%1,%2,%3};"
        : "+f"(c[0]), "+f"(c[1]), "+f"(c[2]), "+f"(c[3])
        : "r"(a0), "r"(a1), "r"(a2), "r"(a3), "r"(b0), "r"(b1));
}

// ---------------------------------------------------------------------------
// K1: dual GEMM on tensor cores (tf32 mma.sync, fp32 accumulate). R9-proven.
// ---------------------------------------------------------------------------
__global__ void __launch_bounds__(128) k_gemm(const float* __restrict__ x,
                                              const float* __restrict__ wl,
                                              const float* __restrict__ bl,
                                              const float* __restrict__ wr) {
    __shared__ unsigned s_x[NODES_BLK][68];   // [node][k] tf32, padded
    __shared__ unsigned s_wl[NF * NC];        // [k][c] tf32
    __shared__ unsigned s_wr[NF * NC];
    __shared__ float    s_b[NC];

    const int tid = threadIdx.x;
    const int n0 = blockIdx.x * NODES_BLK;

    for (int i = tid; i < NF * NC; i += 128) {
        s_wl[i] = cvt_tf32(wl[i]);
        s_wr[i] = cvt_tf32(wr[i]);
    }
    if (tid < NC) s_b[tid] = bl[tid];

    for (int i = tid; i < NODES_BLK * 16; i += 128) {
        int node = i >> 4, kq = i & 15;
        int gn = n0 + node;
        float4 v = make_float4(0.f, 0.f, 0.f, 0.f);
        if (gn < NN) v = reinterpret_cast<const float4*>(x)[gn * 16 + kq];
        s_x[node][kq * 4 + 0] = cvt_tf32(v.x);
        s_x[node][kq * 4 + 1] = cvt_tf32(v.y);
        s_x[node][kq * 4 + 2] = cvt_tf32(v.z);
        s_x[node][kq * 4 + 3] = cvt_tf32(v.w);
    }
    __syncthreads();

    const int w = tid >> 5;
    const int lane = tid & 31;
    const int g = lane >> 2;
    const int t = lane & 3;
    const int wn = w * 16;

    float cy[5][4] = {}, cz[5][4] = {};
#pragma unroll
    for (int k0 = 0; k0 < NF; k0 += 8) {
        unsigned a0 = s_x[wn + g][k0 + t];
        unsigned a1 = s_x[wn + g + 8][k0 + t];
        unsigned a2 = s_x[wn + g][k0 + t + 4];
        unsigned a3 = s_x[wn + g + 8][k0 + t + 4];
#pragma unroll
        for (int nt = 0; nt < 5; nt++) {
            unsigned b0 = s_wl[(k0 + t) * NC + nt * 8 + g];
            unsigned b1 = s_wl[(k0 + t + 4) * NC + nt * 8 + g];
            mma_tf32(cy[nt], a0, a1, a2, a3, b0, b1);
            unsigned d0 = s_wr[(k0 + t) * NC + nt * 8 + g];
            unsigned d1 = s_wr[(k0 + t + 4) * NC + nt * 8 + g];
            mma_tf32(cz[nt], a0, a1, a2, a3, d0, d1);
        }
    }

#pragma unroll
    for (int nt = 0; nt < 5; nt++) {
        int c0 = nt * 8 + 2 * t;
        int nA = n0 + wn + g;
        int nB = nA + 8;
        if (nA < NN) {
            g_yh[nA * 32 + nt * 4 + t] = __floats2half2_rn(cy[nt][0], cy[nt][1]);
            float2 z = make_float2(cz[nt][0] + s_b[c0], cz[nt][1] + s_b[c0 + 1]);
            *reinterpret_cast<float2*>(&g_z[nA * NC + c0]) = z;
        }
        if (nB < NN) {
            g_yh[nB * 32 + nt * 4 + t] = __floats2half2_rn(cy[nt][2], cy[nt][3]);
            float2 z = make_float2(cz[nt][2] + s_b[c0], cz[nt][3] + s_b[c0 + 1]);
            *reinterpret_cast<float2*>(&g_z[nB * NC + c0]) = z;
        }
    }
    for (int i = tid; i < NODES_BLK * 12; i += 128) {
        int node = n0 + i / 12;
        int slot = 20 + i % 12;
        if (node < NN) g_yh[node * 32 + slot] = __floats2half2_rn(0.f, 0.f);
    }
}

// ---------------------------------------------------------------------------
// K2: degree histogram, 4 edges per thread (vector index loads, MLP=4).
// ---------------------------------------------------------------------------
__global__ void __launch_bounds__(256) k_hist(const void* __restrict__ idx_raw) {
    int t = blockIdx.x * 256 + threadIdx.x;
    long long e = (long long)t * 4;
    if (e >= NE) return;
    int d[4];
    load_idx4(idx_raw, (long long)NE + e, d);
    atomicAdd(&g_cnt[d[0]], 1);
    atomicAdd(&g_cnt[d[1]], 1);
    atomicAdd(&g_cnt[d[2]], 1);
    atomicAdd(&g_cnt[d[3]], 1);
}

// K3a: 1024-elem exclusive scan per block
__global__ void __launch_bounds__(256) k_scan1() {
    __shared__ int s[256];
    int base = blockIdx.x * 1024 + threadIdx.x * 4;
    int v0 = (base + 0 < NN) ? g_cnt[base + 0] : 0;
    int v1 = (base + 1 < NN) ? g_cnt[base + 1] : 0;
    int v2 = (base + 2 < NN) ? g_cnt[base + 2] : 0;
    int v3 = (base + 3 < NN) ? g_cnt[base + 3] : 0;
    int tsum = v0 + v1 + v2 + v3;
    s[threadIdx.x] = tsum;
    __syncthreads();
#pragma unroll
    for (int off = 1; off < 256; off <<= 1) {
        int t = (threadIdx.x >= off) ? s[threadIdx.x - off] : 0;
        __syncthreads();
        s[threadIdx.x] += t;
        __syncthreads();
    }
    int excl = s[threadIdx.x] - tsum;
    if (base + 0 < NN) g_off[base + 0] = excl;
    if (base + 1 < NN) g_off[base + 1] = excl + v0;
    if (base + 2 < NN) g_off[base + 2] = excl + v0 + v1;
    if (base + 3 < NN) g_off[base + 3] = excl + v0 + v1 + v2;
    if (threadIdx.x == 255) g_bsums[blockIdx.x] = s[255];
}

// K3b: scan 98 block sums
__global__ void k_scan2() {
    __shared__ int s[128];
    int tid = threadIdx.x;
    int v = (tid < NBLK_SCAN) ? g_bsums[tid] : 0;
    s[tid] = v;
    __syncthreads();
#pragma unroll
    for (int off = 1; off < 128; off <<= 1) {
        int t = (tid >= off) ? s[tid - off] : 0;
        __syncthreads();
        s[tid] += t;
        __syncthreads();
    }
    if (tid < NBLK_SCAN) g_bsums[tid] = s[tid] - v;
}

// K3c: finalize offsets + init cursors
__global__ void __launch_bounds__(256) k_scan3() {
    int n = blockIdx.x * 256 + threadIdx.x;
    if (n >= NN) return;
    int o = g_off[n] + g_bsums[n >> 10];
    g_off[n] = o;
    g_cursor[n] = o;
}

// ---------------------------------------------------------------------------
// K4: CSR fill, 4 edges per thread (vector loads, 4 independent ATOMG chains).
// ---------------------------------------------------------------------------
__global__ void __launch_bounds__(256) k_fill(const void* __restrict__ idx_raw) {
    int t = blockIdx.x * 256 + threadIdx.x;
    long long e = (long long)t * 4;
    if (e >= NE) return;
    int s[4], d[4];
    load_idx4(idx_raw, e, s);
    load_idx4(idx_raw, (long long)NE + e, d);
    int p0 = atomicAdd(&g_cursor[d[0]], 1);
    int p1 = atomicAdd(&g_cursor[d[1]], 1);
    int p2 = atomicAdd(&g_cursor[d[2]], 1);
    int p3 = atomicAdd(&g_cursor[d[3]], 1);
    g_csr[p0] = s[0];
    g_csr[p1] = s[1];
    g_csr[p2] = s[2];
    g_csr[p3] = s[3];
}

// ---------------------------------------------------------------------------
// K5: fused gather-mean + z + log_softmax. Warp per node (proven).
// ---------------------------------------------------------------------------
__global__ void __launch_bounds__(256) k_fused(float* __restrict__ out) {
    int gtid = blockIdx.x * 256 + threadIdx.x;
    int node = gtid >> 5;
    int lane = threadIdx.x & 31;
    if (node >= NN) return;

    int base = g_off[node];
    int deg  = g_cnt[node];

    float2 acc = make_float2(0.f, 0.f);
    for (int j0 = 0; j0 < deg; j0 += 32) {
        int e = (j0 + lane < deg) ? g_csr[base + j0 + lane] : 0;
        int m = min(32, deg - j0);
        for (int k = 0; k < m; k++) {
            int src = __shfl_sync(0xFFFFFFFFu, e, k);
            float2 f = __half22float2(g_yh[src * 32 + lane]);
            acc.x += f.x;
            acc.y += f.y;
        }
    }

    float inv = 1.0f / fmaxf((float)deg, 1.0f);
    const float NEG = -3.0e38f;
    bool valid = lane < 20;
    float2 z2 = valid ? reinterpret_cast<const float2*>(&g_z[node * NC])[lane]
                      : make_float2(0.f, 0.f);
    float va = valid ? fmaf(acc.x, inv, z2.x) : NEG;
    float vb = valid ? fmaf(acc.y, inv, z2.y) : NEG;

    float mx = fmaxf(va, vb);
#pragma unroll
    for (int off = 16; off > 0; off >>= 1)
        mx = fmaxf(mx, __shfl_xor_sync(0xFFFFFFFFu, mx, off));

    float s = valid ? (__expf(va - mx) + __expf(vb - mx)) : 0.0f;
#pragma unroll
    for (int off = 16; off > 0; off >>= 1)
        s += __shfl_xor_sync(0xFFFFFFFFu, s, off);

    float lse = mx + logf(s);
    if (valid) {
        float2 o = make_float2(va - lse, vb - lse);
        reinterpret_cast<float2*>(&out[node * NC])[lane] = o;
    }
}

extern "C" void kernel_launch(void* const* d_in, const int* in_sizes, int n_in,
                              void* d_out, int out_size) {
    const float* x   = (const float*)d_in[0];
    const void*  idx = d_in[1];
    const float* wl  = (const float*)d_in[2];
    const float* bl  = (const float*)d_in[3];
    const float* wr  = (const float*)d_in[4];
    float* out = (float*)d_out;

    k_prep<<<(NN + 255) / 256, 256>>>((const int*)idx);
    k_gemm<<<(NN + NODES_BLK - 1) / NODES_BLK, 128>>>(x, wl, bl, wr);
    k_hist<<<(NE / 4 + 255) / 256, 256>>>(idx);
    k_scan1<<<NBLK_SCAN, 256>>>();
    k_scan2<<<1, 128>>>();
    k_scan3<<<(NN + 255) / 256, 256>>>();
    k_fill<<<(NE / 4 + 255) / 256, 256>>>(idx);
    k_fused<<<(NN * 32 + 255) / 256, 256>>>(out);
}